// round 13
// baseline (speedup 1.0000x reference)
#include <cuda_runtime.h>
#include <cuda_bf16.h>
#include <cstdint>

#define B 64
#define T 512
#define F 256
#define C 1024
#define KOUT 256
#define BC (B * C)
#define WROW (F + C)          // 1280 floats per g_w/a_w row

// ---------------- recurrent kernel config --------------------------------
#define RCTA 128              // (cg 0..63) x (batch-half 0..1)
#define NCG  64               // cell groups
#define RTHR 512              // 16 warps: kq = warp>>2, wn = warp&3
#define CPC  16               // cells per CTA  (A tile M = 32 = 16 a + 16 g)
#define NB   32               // batches per CTA
#define APITCH 1032           // smem A pitch (bf16)
#define A_BYTES (64 * APITCH * 2)              // 132096
// warp-private B ring: 4 stages x 1280 B (2 halves x 8 rows x 80 B)
#define WB_STG 1280
#define WB_NSTG 4
#define WB_WARP (WB_NSTG * WB_STG)             // 5120
#define WB_OFF A_BYTES
#define RED_OFF (WB_OFF + 16 * WB_WARP)        // 214016
#define RSMEM (RED_OFF + 16384)                // 230400

// ---------------- bf16 GEMM (pre/out) config -----------------------------
#define GP 72                                   // smem pitch (bf16)
#define GSTG (128 * GP * 2)                     // 18432 B per operand stage
#define GSTAGE (2 * GSTG)                       // 36864
#define GSMEM (3 * GSTAGE)                      // 110592

// ---------------- device scratch -----------------------------------------
__device__ __align__(16) float g_U [(size_t)T * BC];
__device__ __align__(16) float g_GX[(size_t)T * BC];
__device__ __align__(16) float g_AX[(size_t)T * BC];
__device__ __align__(16) __nv_bfloat16 g_hshi[(size_t)(T + 1) * BC]; // h slots
__device__ __align__(16) __nv_bfloat16 g_hslo[(size_t)(T + 1) * BC];
__device__ __align__(16) __nv_bfloat16 g_Awhi[NCG * 32 * C];  // rec weights
__device__ __align__(16) __nv_bfloat16 g_Awlo[NCG * 32 * C];
__device__ __align__(16) __nv_bfloat16 g_xhi[(size_t)B * T * F];
__device__ __align__(16) __nv_bfloat16 g_xlo[(size_t)B * T * F];
__device__ __align__(16) __nv_bfloat16 g_pwhi[3 * C * F];     // u/gF/aF rows
__device__ __align__(16) __nv_bfloat16 g_pwlo[3 * C * F];
__device__ __align__(16) __nv_bfloat16 g_owhi[KOUT * C];
__device__ __align__(16) __nv_bfloat16 g_owlo[KOUT * C];
__device__ __align__(32) unsigned g_flag[2][8];

// ---------------- helpers -------------------------------------------------
__device__ __forceinline__ uint32_t smem_u32(const void* p) {
    uint32_t a;
    asm("{ .reg .u64 t; cvta.to.shared.u64 t, %1; cvt.u32.u64 %0, t; }"
        : "=r"(a) : "l"(p));
    return a;
}
__device__ __forceinline__ void cpa16(uint32_t dst, const void* src) {
    asm volatile("cp.async.cg.shared.global [%0], [%1], 16;"
                 :: "r"(dst), "l"(src) : "memory");
}
#define CPA_COMMIT() asm volatile("cp.async.commit_group;" ::: "memory")
#define CPA_WAIT(n)  asm volatile("cp.async.wait_group %0;" :: "n"(n) : "memory")

__device__ __forceinline__ void mma16816(float* d, const uint32_t* a,
                                         const uint32_t* b) {
    asm volatile(
        "mma.sync.aligned.m16n8k16.row.col.f32.bf16.bf16.f32 "
        "{%0,%1,%2,%3},{%4,%5,%6,%7},{%8,%9},{%0,%1,%2,%3};"
        : "+f"(d[0]), "+f"(d[1]), "+f"(d[2]), "+f"(d[3])
        : "r"(a[0]), "r"(a[1]), "r"(a[2]), "r"(a[3]), "r"(b[0]), "r"(b[1]));
}
__device__ __forceinline__ void ldm_x4(uint32_t* r, uint32_t a) {
    asm volatile("ldmatrix.sync.aligned.m8n8.x4.shared.b16 {%0,%1,%2,%3}, [%4];"
                 : "=r"(r[0]), "=r"(r[1]), "=r"(r[2]), "=r"(r[3]) : "r"(a));
}
__device__ __forceinline__ void ldm_x2(uint32_t* r, uint32_t a) {
    asm volatile("ldmatrix.sync.aligned.m8n8.x2.shared.b16 {%0,%1}, [%2];"
                 : "=r"(r[0]), "=r"(r[1]) : "r"(a));
}
__device__ __forceinline__ void split_bf16(float v, __nv_bfloat16& hi,
                                           __nv_bfloat16& lo) {
    hi = __float2bfloat16_rn(v);
    lo = __float2bfloat16_rn(v - __bfloat162float(hi));
}
// warp-scoped poll of one chunk flag (all lanes spin on same address)
__device__ __forceinline__ void flag_wait1(const unsigned* f, unsigned tgt) {
    for (;;) {
        unsigned v;
        asm volatile("ld.volatile.global.u32 %0, [%1];" : "=r"(v) : "l"(f));
        if (v >= tgt) return;
    }
}

// ---------------- prep kernels -------------------------------------------
__global__ void wprep_rec(const float* __restrict__ g_w,
                          const float* __restrict__ a_w) {
    int idx = blockIdx.x * blockDim.x + threadIdx.x;   // NCG*32*C
    int cg = idx >> 15, r = (idx >> 10) & 31, k = idx & 1023;
    int cell = cg * CPC + (r & 15);
    const float* src = (r < 16) ? a_w : g_w;
    split_bf16(src[(size_t)cell * WROW + F + k], g_Awhi[idx], g_Awlo[idx]);
}
__global__ void xprep(const float* __restrict__ x) {
    size_t i = (size_t)blockIdx.x * blockDim.x + threadIdx.x;   // B*T*F
    split_bf16(x[i], g_xhi[i], g_xlo[i]);
}
__global__ void pwprep(const float* __restrict__ u_w,
                       const float* __restrict__ g_w,
                       const float* __restrict__ a_w) {
    int idx = blockIdx.x * blockDim.x + threadIdx.x;   // 3*C*F
    int row = idx >> 8, k = idx & 255;
    float v;
    if (row < C)           v = u_w[(size_t)row * F + k];
    else if (row < 2 * C)  v = g_w[(size_t)(row - C) * WROW + k];
    else                   v = a_w[(size_t)(row - 2 * C) * WROW + k];
    split_bf16(v, g_pwhi[idx], g_pwlo[idx]);
}
__global__ void owprep(const float* __restrict__ o_w) {
    int idx = blockIdx.x * blockDim.x + threadIdx.x;   // KOUT*C
    split_bf16(o_w[idx], g_owhi[idx], g_owlo[idx]);
}
__global__ void hinit(const float* __restrict__ h_in,
                      const float* __restrict__ s,
                      float* __restrict__ out_s) {
    int i = blockIdx.x * blockDim.x + threadIdx.x;
    if (i < BC) {
        int c = i & (C - 1);
        split_bf16(h_in[i] + tanhf(s[c]), g_hshi[i], g_hslo[i]);
    }
    if (i < C) out_s[i] = s[i];
    if (i < 16) ((unsigned*)g_flag)[i] = 0u;
}

// ---------------- generic bf16x3 GEMM bodies -----------------------------
struct GemmFrag {
    uint32_t aoff_h[2], aoff_l[2], boff_h[2], boff_l[2];
    int wm, wn, gid, tig, lane;
};
__device__ __forceinline__ GemmFrag gemm_frag(int tid) {
    GemmFrag f;
    int warp = tid >> 5;
    f.lane = tid & 31;
    f.gid = f.lane >> 2;
    f.tig = f.lane & 3;
    f.wm = warp & 1;
    f.wn = warp >> 1;
    int aRow = ((f.lane >> 3) & 1) * 8 + (f.lane & 7);
    int aCol = ((f.lane >> 4) & 1) * 8;
    int bRow = f.lane & 7;
    int bCol = ((f.lane >> 3) & 1) * 8;
#pragma unroll
    for (int mt = 0; mt < 2; ++mt) {
        f.aoff_h[mt] = (uint32_t)((f.wm * 32 + mt * 16 + aRow) * GP + aCol) * 2;
        f.aoff_l[mt] = (uint32_t)((64 + f.wm * 32 + mt * 16 + aRow) * GP + aCol) * 2;
    }
#pragma unroll
    for (int nt = 0; nt < 2; ++nt) {
        f.boff_h[nt] = (uint32_t)((f.wn * 16 + nt * 8 + bRow) * GP + bCol) * 2;
        f.boff_l[nt] = (uint32_t)((64 + f.wn * 16 + nt * 8 + bRow) * GP + bCol) * 2;
    }
    return f;
}
__device__ __forceinline__ void gemm_load_stage(
    uint32_t sb, int stg,
    const __nv_bfloat16* __restrict__ Ahi, const __nv_bfloat16* __restrict__ Alo,
    int lda,
    const __nv_bfloat16* __restrict__ Bhi, const __nv_bfloat16* __restrict__ Blo,
    int ldb, int k0, int tid) {
    uint32_t base = sb + stg * GSTAGE;
#pragma unroll
    for (int j = 0; j < 4; ++j) {
        int g = tid + j * 256;
        int row = g >> 3, q = g & 7;
        const __nv_bfloat16* src = (row < 64)
            ? Ahi + (size_t)row * lda + k0 + q * 8
            : Alo + (size_t)(row - 64) * lda + k0 + q * 8;
        cpa16(base + (uint32_t)(row * GP + q * 8) * 2, src);
    }
#pragma unroll
    for (int j = 0; j < 4; ++j) {
        int g = tid + j * 256;
        int row = g >> 3, q = g & 7;
        const __nv_bfloat16* src = (row < 64)
            ? Bhi + (size_t)row * ldb + k0 + q * 8
            : Blo + (size_t)(row - 64) * ldb + k0 + q * 8;
        cpa16(base + GSTG + (uint32_t)(row * GP + q * 8) * 2, src);
    }
    CPA_COMMIT();
}
__device__ __forceinline__ void gemm_mma_chunk(uint32_t sb, int stg,
                                               const GemmFrag& f,
                                               float acc[2][2][4]) {
    uint32_t stA = sb + stg * GSTAGE;
    uint32_t stB = stA + GSTG;
#pragma unroll
    for (int ks = 0; ks < 4; ++ks) {
        uint32_t kk = ks * 32;                 // bytes
        uint32_t ah[2][4], al[2][4], bh[2][2], bl[2][2];
#pragma unroll
        for (int mt = 0; mt < 2; ++mt) {
            ldm_x4(ah[mt], stA + f.aoff_h[mt] + kk);
            ldm_x4(al[mt], stA + f.aoff_l[mt] + kk);
        }
#pragma unroll
        for (int nt = 0; nt < 2; ++nt) {
            ldm_x2(bh[nt], stB + f.boff_h[nt] + kk);
            ldm_x2(bl[nt], stB + f.boff_l[nt] + kk);
        }
#pragma unroll
        for (int mt = 0; mt < 2; ++mt)
#pragma unroll
            for (int nt = 0; nt < 2; ++nt) {
                mma16816(acc[mt][nt], ah[mt], bh[nt]);
                mma16816(acc[mt][nt], ah[mt], bl[nt]);
                mma16816(acc[mt][nt], al[mt], bh[nt]);
            }
    }
}
__device__ __forceinline__ void gemm_transpose(char* smem, const GemmFrag& f,
                                               float acc[2][2][4]) {
    __syncthreads();
    float* tr = (float*)smem;                  // [n 64][m 64+4]
#pragma unroll
    for (int mt = 0; mt < 2; ++mt)
#pragma unroll
        for (int nt = 0; nt < 2; ++nt)
#pragma unroll
            for (int j = 0; j < 4; ++j) {
                int n = f.wn * 16 + nt * 8 + 2 * f.tig + (j & 1);
                int m = f.wm * 32 + mt * 16 + f.gid + (j >> 1) * 8;
                tr[n * 68 + m] = acc[mt][nt][j];
            }
    __syncthreads();
}

// ---------------- pre GEMM: [U|GX|AX] = x @ W^T + bias -------------------
__global__ void __launch_bounds__(256) pre_gemm_bf16(
    const float* __restrict__ u_b, const float* __restrict__ g_b) {
    extern __shared__ char smem[];
    const uint32_t sb = smem_u32(smem);
    const int tid = threadIdx.x;
    const int n0 = blockIdx.x * 64;            // x rows
    const int m0 = blockIdx.y * 64;            // weight rows (0..3071)
    const GemmFrag f = gemm_frag(tid);

    const __nv_bfloat16* Ahi = g_pwhi + (size_t)m0 * F;
    const __nv_bfloat16* Alo = g_pwlo + (size_t)m0 * F;
    const __nv_bfloat16* Bhi = g_xhi + (size_t)n0 * F;
    const __nv_bfloat16* Blo = g_xlo + (size_t)n0 * F;

    float acc[2][2][4] = {};
    const int NC = F / 64;                     // 4 chunks
    gemm_load_stage(sb, 0, Ahi, Alo, F, Bhi, Blo, F, 0, tid);
    gemm_load_stage(sb, 1, Ahi, Alo, F, Bhi, Blo, F, 64, tid);
    gemm_load_stage(sb, 2, Ahi, Alo, F, Bhi, Blo, F, 128, tid);
#pragma unroll 1
    for (int c = 0; c < NC; ++c) {
        int pend = NC - 1 - c;
        if (pend >= 2) CPA_WAIT(2); else if (pend == 1) CPA_WAIT(1); else CPA_WAIT(0);
        __syncthreads();
        gemm_mma_chunk(sb, c % 3, f, acc);
        if (c + 3 < NC) {
            __syncthreads();
            gemm_load_stage(sb, c % 3, Ahi, Alo, F, Bhi, Blo, F, (c + 3) * 64, tid);
        }
    }
    gemm_transpose(smem, f, acc);

    const int which = m0 >> 10;
    const int cbase = m0 & 1023;
    float* dst = (which == 0) ? g_U : (which == 1) ? g_GX : g_AX;
    const float* bias = (which == 0) ? u_b : (which == 1) ? g_b : nullptr;
    const float* tr = (const float*)smem;
    const int n = tid >> 2;
    const int n_g = n0 + n;
    const int b = n_g >> 9, t = n_g & 511;     // n_g = b*T + t
    float* drow = dst + (size_t)t * BC + (size_t)b * C + cbase;
#pragma unroll
    for (int q = 0; q < 4; ++q) {
        int m = ((tid & 3) * 4 + q) * 4;
        float4 v = *(const float4*)&tr[n * 68 + m];
        if (bias) {
            float4 bv = *(const float4*)&bias[cbase + m];
            v.x += bv.x; v.y += bv.y; v.z += bv.z; v.w += bv.w;
        }
        *(float4*)&drow[m] = v;
    }
}

// ---------------- out GEMM: outs[b][t][:] = h_t @ o_w^T + o_b ------------
__global__ void __launch_bounds__(256) out_gemm_bf16(
    const float* __restrict__ o_b, float* __restrict__ outp) {
    extern __shared__ char smem[];
    const uint32_t sb = smem_u32(smem);
    const int tid = threadIdx.x;
    const int tslot = blockIdx.x;              // t: h_t stored at slot t+1
    const int m0 = blockIdx.y * 64;            // out-class rows
    const GemmFrag f = gemm_frag(tid);

    const __nv_bfloat16* Ahi = g_owhi + (size_t)m0 * C;
    const __nv_bfloat16* Alo = g_owlo + (size_t)m0 * C;
    const __nv_bfloat16* Bhi = g_hshi + (size_t)(tslot + 1) * BC;
    const __nv_bfloat16* Blo = g_hslo + (size_t)(tslot + 1) * BC;

    float acc[2][2][4] = {};
    const int NC = C / 64;                     // 16 chunks
    gemm_load_stage(sb, 0, Ahi, Alo, C, Bhi, Blo, C, 0, tid);
    gemm_load_stage(sb, 1, Ahi, Alo, C, Bhi, Blo, C, 64, tid);
    gemm_load_stage(sb, 2, Ahi, Alo, C, Bhi, Blo, C, 128, tid);
#pragma unroll 1
    for (int c = 0; c < NC; ++c) {
        int pend = NC - 1 - c;
        if (pend >= 2) CPA_WAIT(2); else if (pend == 1) CPA_WAIT(1); else CPA_WAIT(0);
        __syncthreads();
        gemm_mma_chunk(sb, c % 3, f, acc);
        if (c + 3 < NC) {
            __syncthreads();
            gemm_load_stage(sb, c % 3, Ahi, Alo, C, Bhi, Blo, C, (c + 3) * 64, tid);
        }
    }
    gemm_transpose(smem, f, acc);

    const float* tr = (const float*)smem;
    const int b = tid >> 2;                    // n index = batch
    float* drow = outp + (size_t)b * T * KOUT + (size_t)tslot * KOUT + m0;
#pragma unroll
    for (int q = 0; q < 4; ++q) {
        int m = ((tid & 3) * 4 + q) * 4;
        float4 v = *(const float4*)&tr[b * 68 + m];
        float4 bv = *(const float4*)&o_b[m0 + m];
        v.x += bv.x; v.y += bv.y; v.z += bv.z; v.w += bv.w;
        *(float4*)&drow[m] = v;
    }
}

// ---------------- warp-private B slice loader ----------------------------
// Each warp loads ONLY its (wn, kq) slice: 8 rows x 32 cols, hi+lo = 1 KB.
// 64 pieces of 16 B; 2 per lane. Row pitch 80 B (conflict-free ldmatrix).
__device__ __forceinline__ void rec_load_my(
    int p, int s, uint32_t wb, const __nv_bfloat16* __restrict__ hhi,
    const __nv_bfloat16* __restrict__ hlo, int bbase, int wn, int kq,
    int lane) {
#pragma unroll
    for (int j = 0; j < 2; ++j) {
        int i = lane * 2 + j;                  // 0..63
        int half = i >> 5, r = (i >> 2) & 7, q = i & 3;
        uint32_t d = wb + s * WB_STG + half * 640 + r * 80 + q * 16;
        const __nv_bfloat16* src = (half ? hlo : hhi)
            + (size_t)(bbase + wn * 8 + r) * C + p * 128 + kq * 32 + q * 8;
        cpa16(d, src);
    }
    CPA_COMMIT();
}

// ---------------- persistent recurrent kernel ----------------------------
// Per-warp per-chunk flag waits; barrier-free k-loop; depth-3 private ring.
__global__ void __launch_bounds__(RTHR, 1) rec_kernel(
    const float* __restrict__ n_in, const float* __restrict__ d_in,
    const float* __restrict__ amax_in,
    float* __restrict__ out_n, float* __restrict__ out_d,
    float* __restrict__ out_h, float* __restrict__ out_amax) {
    extern __shared__ char smem[];
    const uint32_t sb = smem_u32(smem);
    float* red = (float*)(smem + RED_OFF);     // [4 kq][8 q][128]

    const int tid   = threadIdx.x;
    const int warp  = tid >> 5;
    const int lane  = tid & 31;
    const int wn    = warp & 3;                // n-tile: batches wn*8..+7
    const int kq    = warp >> 2;               // k-quarter (32) within chunk
    const int cg    = blockIdx.x >> 1;
    const int bh    = blockIdx.x & 1;
    const int bbase = bh * NB;
    const int rot   = cg >> 3;                 // starting chunk (0..7)
    const uint32_t wb = sb + WB_OFF + warp * WB_WARP;

    // ---- prologue: resident weights into smem (CTA-shared, once) ----
    for (int i = tid; i < 64 * 128; i += RTHR) {
        int row = i >> 7, q = i & 127;
        const __nv_bfloat16* src = (row < 32)
            ? g_Awhi + ((size_t)cg * 32 + row) * C + q * 8
            : g_Awlo + ((size_t)cg * 32 + row - 32) * C + q * 8;
        cpa16(sb + (uint32_t)(row * APITCH + q * 8) * 2, src);
    }
    CPA_COMMIT();
    CPA_WAIT(0);
    __syncthreads();                           // A tile visible to all warps

    const int aRow = ((lane >> 3) & 1) * 8 + (lane & 7);
    const int aCol = ((lane >> 4) & 1) * 8;
    const uint32_t aHi0 = sb + (uint32_t)((aRow)      * APITCH + aCol) * 2;
    const uint32_t aHi1 = sb + (uint32_t)((16 + aRow) * APITCH + aCol) * 2;
    const uint32_t aLo0 = sb + (uint32_t)((32 + aRow) * APITCH + aCol) * 2;
    const uint32_t aLo1 = sb + (uint32_t)((48 + aRow) * APITCH + aCol) * 2;
    // fused B x4 from warp-private ring: lanes 0-15 hi, 16-31 lo
    const uint32_t bBase = wb + (uint32_t)(lane >> 4) * 640
                         + (uint32_t)(lane & 7) * 80
                         + (uint32_t)((lane >> 3) & 1) * 16;

    // ---- per-thread state: ONE (cell, batch) pair per thread ----
    const int cc = tid & 15;                   // cell within group
    const int nb = tid >> 4;                   // local batch 0..31
    const int bglob = bbase + nb;
    const int cglob = cg * CPC + cc;
    const int p2 = ((cc >> 3) << 1) | (nb & 1);
    const int lane_src = ((cc & 7) << 2) | ((nb & 7) >> 1);
    const int wn_src = nb >> 3;
    const int aidx_base = wn_src * 32 + lane_src;

    float sn = n_in[bglob * C + cglob];
    float sd = d_in[bglob * C + cglob];
    float sa = amax_in[bglob * C + cglob];

    for (int t = 0; t < T; ++t) {
        const __nv_bfloat16* hhi = g_hshi + (size_t)t * BC;
        const __nv_bfloat16* hlo = g_hslo + (size_t)t * BC;
        const unsigned tgt = 8u * (unsigned)t;
        const unsigned* flags = &g_flag[bh][0];

        // epilogue-operand prefetch (DRAM, hidden under MMA loop)
        const size_t tb = (size_t)t * BC;
        const size_t eidx = tb + (size_t)bglob * C + cglob;
        float ax = __ldg(&g_AX[eidx]);
        float gx = __ldg(&g_GX[eidx]);
        float ux = __ldg(&g_U[eidx]);

        // per-warp pipeline: 3 chunks in flight, each gated by its own flag
        flag_wait1(flags + rot, tgt);
        rec_load_my(rot, 0, wb, hhi, hlo, bbase, wn, kq, lane);
        flag_wait1(flags + ((rot + 1) & 7), tgt);
        rec_load_my((rot + 1) & 7, 1, wb, hhi, hlo, bbase, wn, kq, lane);
        flag_wait1(flags + ((rot + 2) & 7), tgt);
        rec_load_my((rot + 2) & 7, 2, wb, hhi, hlo, bbase, wn, kq, lane);

        float acc[8];
#pragma unroll
        for (int q = 0; q < 8; ++q) acc[q] = 0.f;

#pragma unroll 1
        for (int i = 0; i < 8; ++i) {
            const int p = (rot + i) & 7;
            if (i <= 5) CPA_WAIT(2);
            else if (i == 6) CPA_WAIT(1);
            else CPA_WAIT(0);
            if (i < 5) {
                const int pn = (rot + i + 3) & 7;
                flag_wait1(flags + pn, tgt);
                rec_load_my(pn, (i + 3) & 3, wb, hhi, hlo, bbase, wn, kq, lane);
            }
            const uint32_t bs = bBase + (uint32_t)((i & 3) * WB_STG);
#pragma unroll
            for (int ks = 0; ks < 2; ++ks) {
                const int ka = p * 128 + kq * 32 + ks * 16;
                uint32_t ah0[4], ah1[4], al0[4], al1[4], bf[4];
                ldm_x4(ah0, aHi0 + ka * 2);
                ldm_x4(ah1, aHi1 + ka * 2);
                ldm_x4(bf,  bs + ks * 32);          // {bh, bl} fused
                ldm_x4(al0, aLo0 + ka * 2);
                ldm_x4(al1, aLo1 + ka * 2);
                mma16816(acc + 0, ah0, bf);
                mma16816(acc + 4, ah1, bf);
                mma16816(acc + 0, ah0, bf + 2);
                mma16816(acc + 4, ah1, bf + 2);
                mma16816(acc + 0, al0, bf);
                mma16816(acc + 4, al1, bf);
            }
        }

        // ---- all-warp partial dump, all-thread epilogue ----
        {
            float* dst = red + (kq * 8) * 128 + wn * 32 + lane;
#pragma unroll
            for (int q = 0; q < 8; ++q) dst[q * 128] = acc[q];
        }
        __syncthreads();
        {
            float at = ax, gt = gx;
#pragma unroll
            for (int k2 = 0; k2 < 4; ++k2) {
                at += red[(k2 * 8 + p2) * 128 + aidx_base];
                gt += red[(k2 * 8 + 4 + p2) * 128 + aidx_base];
            }
            float z  = ux * tanhf(gt);
            float an = fmaxf(sa, at);
            float ed = expf(sa - an);
            float es = expf(at - an);
            sn = sn * ed + z * es;
            sd = sd * ed + es;
            float h = tanhf(sn / sd);
            sa = an;
            __nv_bfloat16 hi, lo;
            split_bf16(h, hi, lo);
            g_hshi[(size_t)(t + 1) * BC + bglob * C + cglob] = hi;
            g_hslo[(size_t)(t + 1) * BC + bglob * C + cglob] = lo;
        }
        __syncthreads();                       // h stores done CTA-wide
        if (tid == 0) {                        // barrier + 1-thread fence
            __threadfence();
            atomicAdd(&g_flag[bh][rot], 1u);
        }
    }

    out_n[bglob * C + cglob]    = sn;
    out_d[bglob * C + cglob]    = sd;
    out_h[bglob * C + cglob]    = tanhf(sn / sd);
    out_amax[bglob * C + cglob] = sa;
}

// ---------------- launch ---------------------------------------------------
extern "C" void kernel_launch(void* const* d_in, const int* in_sizes, int n_in,
                              void* d_out, int out_size) {
    (void)in_sizes; (void)n_in; (void)out_size;
    const float* x      = (const float*)d_in[0];
    const float* s      = (const float*)d_in[1];
    const float* n0     = (const float*)d_in[2];
    const float* d0     = (const float*)d_in[3];
    const float* h0     = (const float*)d_in[4];
    const float* amax0  = (const float*)d_in[5];
    const float* u_w    = (const float*)d_in[6];
    const float* u_b    = (const float*)d_in[7];
    const float* g_w    = (const float*)d_in[8];
    const float* g_b    = (const float*)d_in[9];
    const float* a_w    = (const float*)d_in[10];
    const float* o_w    = (const float*)d_in[11];
    const float* o_b    = (const float*)d_in[12];

    float* out        = (float*)d_out;
    float* out_outs   = out;
    float* out_s      = out + (size_t)B * T * KOUT;
    float* out_n      = out_s + C;
    float* out_d      = out_n + (size_t)B * C;
    float* out_h      = out_d + (size_t)B * C;
    float* out_amax   = out_h + (size_t)B * C;

    cudaFuncSetAttribute(rec_kernel, cudaFuncAttributeMaxDynamicSharedMemorySize, RSMEM);
    cudaFuncSetAttribute(pre_gemm_bf16, cudaFuncAttributeMaxDynamicSharedMemorySize, GSMEM);
    cudaFuncSetAttribute(out_gemm_bf16, cudaFuncAttributeMaxDynamicSharedMemorySize, GSMEM);

    wprep_rec<<<NCG * 32 * C / 256, 256>>>(g_w, a_w);
    xprep<<<(B * T * F) / 256, 256>>>(x);
    pwprep<<<(3 * C * F) / 256, 256>>>(u_w, g_w, a_w);
    owprep<<<(KOUT * C) / 256, 256>>>(o_w);
    hinit<<<(BC + 255) / 256, 256>>>(h0, s, out_s);
    pre_gemm_bf16<<<dim3(512, 48), 256, GSMEM>>>(u_b, g_b);
    rec_kernel<<<RCTA, RTHR, RSMEM>>>(n0, d0, amax0,
                                      out_n, out_d, out_h, out_amax);
    out_gemm_bf16<<<dim3(512, 4), 256, GSMEM>>>(o_b, out_outs);
}

// round 14
// speedup vs baseline: 2.1791x; 2.1791x over previous
#include <cuda_runtime.h>
#include <cuda_bf16.h>
#include <cstdint>

#define B 64
#define T 512
#define F 256
#define C 1024
#define KOUT 256
#define BC (B * C)
#define WROW (F + C)          // 1280 floats per g_w/a_w row

// ---------------- recurrent kernel config --------------------------------
#define RCTA 128              // (cg 0..63) x (batch-half 0..1)
#define NCG  64               // cell groups
#define RTHR 544              // 16 compute warps + 1 sync-relay warp
#define NCW  512              // compute threads
#define CPC  16               // cells per CTA  (A tile M = 32 = 16 a + 16 g)
#define NB   32               // batches per CTA
#define APITCH 1032           // smem A pitch (bf16)
#define A_BYTES (64 * APITCH * 2)              // 132096
// warp-private B ring: 4 stages x 1280 B (2 halves x 8 rows x 80 B)
#define WB_STG 1280
#define WB_NSTG 4
#define WB_WARP (WB_NSTG * WB_STG)             // 5120
#define WB_OFF A_BYTES
#define RED_OFF (WB_OFF + 16 * WB_WARP)        // 214016
#define MBOX_OFF (RED_OFF + 16384)             // 230400
#define RSMEM (MBOX_OFF + 64)                  // 230464

// ---------------- bf16 GEMM (pre/out) config -----------------------------
#define GP 72                                   // smem pitch (bf16)
#define GSTG (128 * GP * 2)                     // 18432 B per operand stage
#define GSTAGE (2 * GSTG)                       // 36864
#define GSMEM (3 * GSTAGE)                      // 110592

// ---------------- device scratch -----------------------------------------
__device__ __align__(16) float g_U [(size_t)T * BC];
__device__ __align__(16) float g_GX[(size_t)T * BC];
__device__ __align__(16) float g_AX[(size_t)T * BC];
__device__ __align__(16) __nv_bfloat16 g_hshi[(size_t)(T + 1) * BC]; // h slots
__device__ __align__(16) __nv_bfloat16 g_hslo[(size_t)(T + 1) * BC];
__device__ __align__(16) __nv_bfloat16 g_Awhi[NCG * 32 * C];  // rec weights
__device__ __align__(16) __nv_bfloat16 g_Awlo[NCG * 32 * C];
__device__ __align__(16) __nv_bfloat16 g_xhi[(size_t)B * T * F];
__device__ __align__(16) __nv_bfloat16 g_xlo[(size_t)B * T * F];
__device__ __align__(16) __nv_bfloat16 g_pwhi[3 * C * F];     // u/gF/aF rows
__device__ __align__(16) __nv_bfloat16 g_pwlo[3 * C * F];
__device__ __align__(16) __nv_bfloat16 g_owhi[KOUT * C];
__device__ __align__(16) __nv_bfloat16 g_owlo[KOUT * C];
__device__ __align__(32) unsigned g_flag[2][8];

// ---------------- helpers -------------------------------------------------
__device__ __forceinline__ uint32_t smem_u32(const void* p) {
    uint32_t a;
    asm("{ .reg .u64 t; cvta.to.shared.u64 t, %1; cvt.u32.u64 %0, t; }"
        : "=r"(a) : "l"(p));
    return a;
}
__device__ __forceinline__ void cpa16(uint32_t dst, const void* src) {
    asm volatile("cp.async.cg.shared.global [%0], [%1], 16;"
                 :: "r"(dst), "l"(src) : "memory");
}
#define CPA_COMMIT() asm volatile("cp.async.commit_group;" ::: "memory")
#define CPA_WAIT(n)  asm volatile("cp.async.wait_group %0;" :: "n"(n) : "memory")

__device__ __forceinline__ void mma16816(float* d, const uint32_t* a,
                                         const uint32_t* b) {
    asm volatile(
        "mma.sync.aligned.m16n8k16.row.col.f32.bf16.bf16.f32 "
        "{%0,%1,%2,%3},{%4,%5,%6,%7},{%8,%9},{%0,%1,%2,%3};"
        : "+f"(d[0]), "+f"(d[1]), "+f"(d[2]), "+f"(d[3])
        : "r"(a[0]), "r"(a[1]), "r"(a[2]), "r"(a[3]), "r"(b[0]), "r"(b[1]));
}
__device__ __forceinline__ void ldm_x4(uint32_t* r, uint32_t a) {
    asm volatile("ldmatrix.sync.aligned.m8n8.x4.shared.b16 {%0,%1,%2,%3}, [%4];"
                 : "=r"(r[0]), "=r"(r[1]), "=r"(r[2]), "=r"(r[3]) : "r"(a));
}
__device__ __forceinline__ void ldm_x2(uint32_t* r, uint32_t a) {
    asm volatile("ldmatrix.sync.aligned.m8n8.x2.shared.b16 {%0,%1}, [%2];"
                 : "=r"(r[0]), "=r"(r[1]) : "r"(a));
}
__device__ __forceinline__ void split_bf16(float v, __nv_bfloat16& hi,
                                           __nv_bfloat16& lo) {
    hi = __float2bfloat16_rn(v);
    lo = __float2bfloat16_rn(v - __bfloat162float(hi));
}

// ---------------- prep kernels -------------------------------------------
__global__ void wprep_rec(const float* __restrict__ g_w,
                          const float* __restrict__ a_w) {
    int idx = blockIdx.x * blockDim.x + threadIdx.x;   // NCG*32*C
    int cg = idx >> 15, r = (idx >> 10) & 31, k = idx & 1023;
    int cell = cg * CPC + (r & 15);
    const float* src = (r < 16) ? a_w : g_w;
    split_bf16(src[(size_t)cell * WROW + F + k], g_Awhi[idx], g_Awlo[idx]);
}
__global__ void xprep(const float* __restrict__ x) {
    size_t i = (size_t)blockIdx.x * blockDim.x + threadIdx.x;   // B*T*F
    split_bf16(x[i], g_xhi[i], g_xlo[i]);
}
__global__ void pwprep(const float* __restrict__ u_w,
                       const float* __restrict__ g_w,
                       const float* __restrict__ a_w) {
    int idx = blockIdx.x * blockDim.x + threadIdx.x;   // 3*C*F
    int row = idx >> 8, k = idx & 255;
    float v;
    if (row < C)           v = u_w[(size_t)row * F + k];
    else if (row < 2 * C)  v = g_w[(size_t)(row - C) * WROW + k];
    else                   v = a_w[(size_t)(row - 2 * C) * WROW + k];
    split_bf16(v, g_pwhi[idx], g_pwlo[idx]);
}
__global__ void owprep(const float* __restrict__ o_w) {
    int idx = blockIdx.x * blockDim.x + threadIdx.x;   // KOUT*C
    split_bf16(o_w[idx], g_owhi[idx], g_owlo[idx]);
}
__global__ void hinit(const float* __restrict__ h_in,
                      const float* __restrict__ s,
                      float* __restrict__ out_s) {
    int i = blockIdx.x * blockDim.x + threadIdx.x;
    if (i < BC) {
        int c = i & (C - 1);
        split_bf16(h_in[i] + tanhf(s[c]), g_hshi[i], g_hslo[i]);
    }
    if (i < C) out_s[i] = s[i];
    if (i < 16) ((unsigned*)g_flag)[i] = 0u;
}

// ---------------- generic bf16x3 GEMM bodies -----------------------------
struct GemmFrag {
    uint32_t aoff_h[2], aoff_l[2], boff_h[2], boff_l[2];
    int wm, wn, gid, tig, lane;
};
__device__ __forceinline__ GemmFrag gemm_frag(int tid) {
    GemmFrag f;
    int warp = tid >> 5;
    f.lane = tid & 31;
    f.gid = f.lane >> 2;
    f.tig = f.lane & 3;
    f.wm = warp & 1;
    f.wn = warp >> 1;
    int aRow = ((f.lane >> 3) & 1) * 8 + (f.lane & 7);
    int aCol = ((f.lane >> 4) & 1) * 8;
    int bRow = f.lane & 7;
    int bCol = ((f.lane >> 3) & 1) * 8;
#pragma unroll
    for (int mt = 0; mt < 2; ++mt) {
        f.aoff_h[mt] = (uint32_t)((f.wm * 32 + mt * 16 + aRow) * GP + aCol) * 2;
        f.aoff_l[mt] = (uint32_t)((64 + f.wm * 32 + mt * 16 + aRow) * GP + aCol) * 2;
    }
#pragma unroll
    for (int nt = 0; nt < 2; ++nt) {
        f.boff_h[nt] = (uint32_t)((f.wn * 16 + nt * 8 + bRow) * GP + bCol) * 2;
        f.boff_l[nt] = (uint32_t)((64 + f.wn * 16 + nt * 8 + bRow) * GP + bCol) * 2;
    }
    return f;
}
__device__ __forceinline__ void gemm_load_stage(
    uint32_t sb, int stg,
    const __nv_bfloat16* __restrict__ Ahi, const __nv_bfloat16* __restrict__ Alo,
    int lda,
    const __nv_bfloat16* __restrict__ Bhi, const __nv_bfloat16* __restrict__ Blo,
    int ldb, int k0, int tid) {
    uint32_t base = sb + stg * GSTAGE;
#pragma unroll
    for (int j = 0; j < 4; ++j) {
        int g = tid + j * 256;
        int row = g >> 3, q = g & 7;
        const __nv_bfloat16* src = (row < 64)
            ? Ahi + (size_t)row * lda + k0 + q * 8
            : Alo + (size_t)(row - 64) * lda + k0 + q * 8;
        cpa16(base + (uint32_t)(row * GP + q * 8) * 2, src);
    }
#pragma unroll
    for (int j = 0; j < 4; ++j) {
        int g = tid + j * 256;
        int row = g >> 3, q = g & 7;
        const __nv_bfloat16* src = (row < 64)
            ? Bhi + (size_t)row * ldb + k0 + q * 8
            : Blo + (size_t)(row - 64) * ldb + k0 + q * 8;
        cpa16(base + GSTG + (uint32_t)(row * GP + q * 8) * 2, src);
    }
    CPA_COMMIT();
}
__device__ __forceinline__ void gemm_mma_chunk(uint32_t sb, int stg,
                                               const GemmFrag& f,
                                               float acc[2][2][4]) {
    uint32_t stA = sb + stg * GSTAGE;
    uint32_t stB = stA + GSTG;
#pragma unroll
    for (int ks = 0; ks < 4; ++ks) {
        uint32_t kk = ks * 32;                 // bytes
        uint32_t ah[2][4], al[2][4], bh[2][2], bl[2][2];
#pragma unroll
        for (int mt = 0; mt < 2; ++mt) {
            ldm_x4(ah[mt], stA + f.aoff_h[mt] + kk);
            ldm_x4(al[mt], stA + f.aoff_l[mt] + kk);
        }
#pragma unroll
        for (int nt = 0; nt < 2; ++nt) {
            ldm_x2(bh[nt], stB + f.boff_h[nt] + kk);
            ldm_x2(bl[nt], stB + f.boff_l[nt] + kk);
        }
#pragma unroll
        for (int mt = 0; mt < 2; ++mt)
#pragma unroll
            for (int nt = 0; nt < 2; ++nt) {
                mma16816(acc[mt][nt], ah[mt], bh[nt]);
                mma16816(acc[mt][nt], ah[mt], bl[nt]);
                mma16816(acc[mt][nt], al[mt], bh[nt]);
            }
    }
}
__device__ __forceinline__ void gemm_transpose(char* smem, const GemmFrag& f,
                                               float acc[2][2][4]) {
    __syncthreads();
    float* tr = (float*)smem;                  // [n 64][m 64+4]
#pragma unroll
    for (int mt = 0; mt < 2; ++mt)
#pragma unroll
        for (int nt = 0; nt < 2; ++nt)
#pragma unroll
            for (int j = 0; j < 4; ++j) {
                int n = f.wn * 16 + nt * 8 + 2 * f.tig + (j & 1);
                int m = f.wm * 32 + mt * 16 + f.gid + (j >> 1) * 8;
                tr[n * 68 + m] = acc[mt][nt][j];
            }
    __syncthreads();
}

// ---------------- pre GEMM: [U|GX|AX] = x @ W^T + bias -------------------
__global__ void __launch_bounds__(256) pre_gemm_bf16(
    const float* __restrict__ u_b, const float* __restrict__ g_b) {
    extern __shared__ char smem[];
    const uint32_t sb = smem_u32(smem);
    const int tid = threadIdx.x;
    const int n0 = blockIdx.x * 64;            // x rows
    const int m0 = blockIdx.y * 64;            // weight rows (0..3071)
    const GemmFrag f = gemm_frag(tid);

    const __nv_bfloat16* Ahi = g_pwhi + (size_t)m0 * F;
    const __nv_bfloat16* Alo = g_pwlo + (size_t)m0 * F;
    const __nv_bfloat16* Bhi = g_xhi + (size_t)n0 * F;
    const __nv_bfloat16* Blo = g_xlo + (size_t)n0 * F;

    float acc[2][2][4] = {};
    const int NC = F / 64;                     // 4 chunks
    gemm_load_stage(sb, 0, Ahi, Alo, F, Bhi, Blo, F, 0, tid);
    gemm_load_stage(sb, 1, Ahi, Alo, F, Bhi, Blo, F, 64, tid);
    gemm_load_stage(sb, 2, Ahi, Alo, F, Bhi, Blo, F, 128, tid);
#pragma unroll 1
    for (int c = 0; c < NC; ++c) {
        int pend = NC - 1 - c;
        if (pend >= 2) CPA_WAIT(2); else if (pend == 1) CPA_WAIT(1); else CPA_WAIT(0);
        __syncthreads();
        gemm_mma_chunk(sb, c % 3, f, acc);
        if (c + 3 < NC) {
            __syncthreads();
            gemm_load_stage(sb, c % 3, Ahi, Alo, F, Bhi, Blo, F, (c + 3) * 64, tid);
        }
    }
    gemm_transpose(smem, f, acc);

    const int which = m0 >> 10;
    const int cbase = m0 & 1023;
    float* dst = (which == 0) ? g_U : (which == 1) ? g_GX : g_AX;
    const float* bias = (which == 0) ? u_b : (which == 1) ? g_b : nullptr;
    const float* tr = (const float*)smem;
    const int n = tid >> 2;
    const int n_g = n0 + n;
    const int b = n_g >> 9, t = n_g & 511;     // n_g = b*T + t
    float* drow = dst + (size_t)t * BC + (size_t)b * C + cbase;
#pragma unroll
    for (int q = 0; q < 4; ++q) {
        int m = ((tid & 3) * 4 + q) * 4;
        float4 v = *(const float4*)&tr[n * 68 + m];
        if (bias) {
            float4 bv = *(const float4*)&bias[cbase + m];
            v.x += bv.x; v.y += bv.y; v.z += bv.z; v.w += bv.w;
        }
        *(float4*)&drow[m] = v;
    }
}

// ---------------- out GEMM: outs[b][t][:] = h_t @ o_w^T + o_b ------------
__global__ void __launch_bounds__(256) out_gemm_bf16(
    const float* __restrict__ o_b, float* __restrict__ outp) {
    extern __shared__ char smem[];
    const uint32_t sb = smem_u32(smem);
    const int tid = threadIdx.x;
    const int tslot = blockIdx.x;              // t: h_t stored at slot t+1
    const int m0 = blockIdx.y * 64;            // out-class rows
    const GemmFrag f = gemm_frag(tid);

    const __nv_bfloat16* Ahi = g_owhi + (size_t)m0 * C;
    const __nv_bfloat16* Alo = g_owlo + (size_t)m0 * C;
    const __nv_bfloat16* Bhi = g_hshi + (size_t)(tslot + 1) * BC;
    const __nv_bfloat16* Blo = g_hslo + (size_t)(tslot + 1) * BC;

    float acc[2][2][4] = {};
    const int NC = C / 64;                     // 16 chunks
    gemm_load_stage(sb, 0, Ahi, Alo, C, Bhi, Blo, C, 0, tid);
    gemm_load_stage(sb, 1, Ahi, Alo, C, Bhi, Blo, C, 64, tid);
    gemm_load_stage(sb, 2, Ahi, Alo, C, Bhi, Blo, C, 128, tid);
#pragma unroll 1
    for (int c = 0; c < NC; ++c) {
        int pend = NC - 1 - c;
        if (pend >= 2) CPA_WAIT(2); else if (pend == 1) CPA_WAIT(1); else CPA_WAIT(0);
        __syncthreads();
        gemm_mma_chunk(sb, c % 3, f, acc);
        if (c + 3 < NC) {
            __syncthreads();
            gemm_load_stage(sb, c % 3, Ahi, Alo, C, Bhi, Blo, C, (c + 3) * 64, tid);
        }
    }
    gemm_transpose(smem, f, acc);

    const float* tr = (const float*)smem;
    const int b = tid >> 2;                    // n index = batch
    float* drow = outp + (size_t)b * T * KOUT + (size_t)tslot * KOUT + m0;
#pragma unroll
    for (int q = 0; q < 4; ++q) {
        int m = ((tid & 3) * 4 + q) * 4;
        float4 v = *(const float4*)&tr[b * 68 + m];
        float4 bv = *(const float4*)&o_b[m0 + m];
        v.x += bv.x; v.y += bv.y; v.z += bv.z; v.w += bv.w;
        *(float4*)&drow[m] = v;
    }
}

// ---------------- warp-private B slice loader ----------------------------
__device__ __forceinline__ void rec_load_my(
    int p, int s, uint32_t wb, const __nv_bfloat16* __restrict__ hhi,
    const __nv_bfloat16* __restrict__ hlo, int bbase, int wn, int kq,
    int lane) {
#pragma unroll
    for (int j = 0; j < 2; ++j) {
        int i = lane * 2 + j;                  // 0..63
        int half = i >> 5, r = (i >> 2) & 7, q = i & 3;
        uint32_t d = wb + s * WB_STG + half * 640 + r * 80 + q * 16;
        const __nv_bfloat16* src = (half ? hlo : hhi)
            + (size_t)(bbase + wn * 8 + r) * C + p * 128 + kq * 32 + q * 8;
        cpa16(d, src);
    }
    CPA_COMMIT();
}
// compute-warp spin on smem mailbox (no L2 traffic)
__device__ __forceinline__ void mbox_wait(volatile unsigned* m, unsigned tgt) {
    while (*m < tgt) {}
}

// ---------------- persistent recurrent kernel ----------------------------
// 16 compute warps + 1 sync-relay warp; per-chunk gating via smem mailbox.
__global__ void __launch_bounds__(RTHR, 1) rec_kernel(
    const float* __restrict__ n_in, const float* __restrict__ d_in,
    const float* __restrict__ amax_in,
    float* __restrict__ out_n, float* __restrict__ out_d,
    float* __restrict__ out_h, float* __restrict__ out_amax) {
    extern __shared__ char smem[];
    const uint32_t sb = smem_u32(smem);
    float* red = (float*)(smem + RED_OFF);     // [4 kq][8 q][128]
    volatile unsigned* mbox = (volatile unsigned*)(smem + MBOX_OFF);

    const int tid   = threadIdx.x;
    const int warp  = tid >> 5;
    const int lane  = tid & 31;
    const bool comp = (warp < 16);
    const int wn    = warp & 3;
    const int kq    = warp >> 2;               // valid for comp warps
    const int cg    = blockIdx.x >> 1;
    const int bh    = blockIdx.x & 1;
    const int bbase = bh * NB;
    const int rot   = cg >> 3;                 // starting chunk (0..7)
    const uint32_t wb = sb + WB_OFF + warp * WB_WARP;

    // ---- prologue: resident weights into smem (all warps help) ----
    for (int i = tid; i < 64 * 128; i += RTHR) {
        int row = i >> 7, q = i & 127;
        const __nv_bfloat16* src = (row < 32)
            ? g_Awhi + ((size_t)cg * 32 + row) * C + q * 8
            : g_Awlo + ((size_t)cg * 32 + row - 32) * C + q * 8;
        cpa16(sb + (uint32_t)(row * APITCH + q * 8) * 2, src);
    }
    CPA_COMMIT();
    if (tid < 8) mbox[tid] = 0u;
    CPA_WAIT(0);
    __syncthreads();                           // A tile + mailbox visible

    const int aRow = ((lane >> 3) & 1) * 8 + (lane & 7);
    const int aCol = ((lane >> 4) & 1) * 8;
    const uint32_t aHi0 = sb + (uint32_t)((aRow)      * APITCH + aCol) * 2;
    const uint32_t aHi1 = sb + (uint32_t)((16 + aRow) * APITCH + aCol) * 2;
    const uint32_t aLo0 = sb + (uint32_t)((32 + aRow) * APITCH + aCol) * 2;
    const uint32_t aLo1 = sb + (uint32_t)((48 + aRow) * APITCH + aCol) * 2;
    const uint32_t bBase = wb + (uint32_t)(lane >> 4) * 640
                         + (uint32_t)(lane & 7) * 80
                         + (uint32_t)((lane >> 3) & 1) * 16;

    // ---- per-thread state (compute threads only) ----
    const int cc = tid & 15;
    const int nb = (tid >> 4) & 31;
    const int bglob = bbase + nb;
    const int cglob = cg * CPC + cc;
    const int p2 = ((cc >> 3) << 1) | (nb & 1);
    const int lane_src = ((cc & 7) << 2) | ((nb & 7) >> 1);
    const int wn_src = nb >> 3;
    const int aidx_base = wn_src * 32 + lane_src;

    float sn = 0.f, sd = 0.f, sa = 0.f;
    if (comp) {
        sn = n_in[bglob * C + cglob];
        sd = d_in[bglob * C + cglob];
        sa = amax_in[bglob * C + cglob];
    }

    for (int t = 0; t < T; ++t) {
        const __nv_bfloat16* hhi = g_hshi + (size_t)t * BC;
        const __nv_bfloat16* hlo = g_hslo + (size_t)t * BC;
        const unsigned tgt = 8u * (unsigned)t;

        if (!comp) {
            // ---- sync-relay warp: poll L2 flags, publish to smem mailbox ----
            unsigned done = (lane < 8) ? 0u : 1u;
            const unsigned* fp = &g_flag[bh][lane & 7];
            while (__ballot_sync(0xFFFFFFFFu, done) != 0xFFFFFFFFu) {
                if (!done) {
                    unsigned v;
                    asm volatile("ld.volatile.global.u32 %0, [%1];"
                                 : "=r"(v) : "l"(fp));
                    if (v >= tgt) { mbox[lane] = v; done = 1u; }
                }
            }
        } else {
            // ---- compute warps: per-chunk gated, barrier-free k-loop ----
            const size_t tb = (size_t)t * BC;
            const size_t eidx = tb + (size_t)bglob * C + cglob;
            float ax = __ldg(&g_AX[eidx]);
            float gx = __ldg(&g_GX[eidx]);
            float ux = __ldg(&g_U[eidx]);

            mbox_wait(mbox + rot, tgt);
            rec_load_my(rot, 0, wb, hhi, hlo, bbase, wn, kq, lane);
            mbox_wait(mbox + ((rot + 1) & 7), tgt);
            rec_load_my((rot + 1) & 7, 1, wb, hhi, hlo, bbase, wn, kq, lane);
            mbox_wait(mbox + ((rot + 2) & 7), tgt);
            rec_load_my((rot + 2) & 7, 2, wb, hhi, hlo, bbase, wn, kq, lane);

            float acc[8];
#pragma unroll
            for (int q = 0; q < 8; ++q) acc[q] = 0.f;

#pragma unroll 1
            for (int i = 0; i < 8; ++i) {
                const int p = (rot + i) & 7;
                if (i <= 5) CPA_WAIT(2);
                else if (i == 6) CPA_WAIT(1);
                else CPA_WAIT(0);
                if (i < 5) {
                    const int pn = (rot + i + 3) & 7;
                    mbox_wait(mbox + pn, tgt);
                    rec_load_my(pn, (i + 3) & 3, wb, hhi, hlo, bbase, wn, kq,
                                lane);
                }
                const uint32_t bs = bBase + (uint32_t)((i & 3) * WB_STG);
#pragma unroll
                for (int ks = 0; ks < 2; ++ks) {
                    const int ka = p * 128 + kq * 32 + ks * 16;
                    uint32_t ah0[4], ah1[4], al0[4], al1[4], bf[4];
                    ldm_x4(ah0, aHi0 + ka * 2);
                    ldm_x4(ah1, aHi1 + ka * 2);
                    ldm_x4(bf,  bs + ks * 32);
                    ldm_x4(al0, aLo0 + ka * 2);
                    ldm_x4(al1, aLo1 + ka * 2);
                    mma16816(acc + 0, ah0, bf);
                    mma16816(acc + 4, ah1, bf);
                    mma16816(acc + 0, ah0, bf + 2);
                    mma16816(acc + 4, ah1, bf + 2);
                    mma16816(acc + 0, al0, bf);
                    mma16816(acc + 4, al1, bf);
                }
            }

            float* dst = red + (kq * 8) * 128 + wn * 32 + lane;
#pragma unroll
            for (int q = 0; q < 8; ++q) dst[q * 128] = acc[q];

            __syncthreads();                   // barrier 1 (partials ready)
            {
                float at = ax, gt = gx;
#pragma unroll
                for (int k2 = 0; k2 < 4; ++k2) {
                    at += red[(k2 * 8 + p2) * 128 + aidx_base];
                    gt += red[(k2 * 8 + 4 + p2) * 128 + aidx_base];
                }
                float z  = ux * tanhf(gt);
                float an = fmaxf(sa, at);
                float ed = expf(sa - an);
                float es = expf(at - an);
                sn = sn * ed + z * es;
                sd = sd * ed + es;
                float h = tanhf(sn / sd);
                sa = an;
                __nv_bfloat16 hi, lo;
                split_bf16(h, hi, lo);
                g_hshi[(size_t)(t + 1) * BC + bglob * C + cglob] = hi;
                g_hslo[(size_t)(t + 1) * BC + bglob * C + cglob] = lo;
            }
            __syncthreads();                   // barrier 2 (h stores done)
            if (tid == 0) {
                __threadfence();
                atomicAdd(&g_flag[bh][rot], 1u);
            }
            continue;
        }
        // sync warp joins the two per-step barriers
        __syncthreads();                       // barrier 1
        __syncthreads();                       // barrier 2
    }

    if (comp) {
        out_n[bglob * C + cglob]    = sn;
        out_d[bglob * C + cglob]    = sd;
        out_h[bglob * C + cglob]    = tanhf(sn / sd);
        out_amax[bglob * C + cglob] = sa;
    }
}

// ---------------- launch ---------------------------------------------------
extern "C" void kernel_launch(void* const* d_in, const int* in_sizes, int n_in,
                              void* d_out, int out_size) {
    (void)in_sizes; (void)n_in; (void)out_size;
    const float* x      = (const float*)d_in[0];
    const float* s      = (const float*)d_in[1];
    const float* n0     = (const float*)d_in[2];
    const float* d0     = (const float*)d_in[3];
    const float* h0     = (const float*)d_in[4];
    const float* amax0  = (const float*)d_in[5];
    const float* u_w    = (const float*)d_in[6];
    const float* u_b    = (const float*)d_in[7];
    const float* g_w    = (const float*)d_in[8];
    const float* g_b    = (const float*)d_in[9];
    const float* a_w    = (const float*)d_in[10];
    const float* o_w    = (const float*)d_in[11];
    const float* o_b    = (const float*)d_in[12];

    float* out        = (float*)d_out;
    float* out_outs   = out;
    float* out_s      = out + (size_t)B * T * KOUT;
    float* out_n      = out_s + C;
    float* out_d      = out_n + (size_t)B * C;
    float* out_h      = out_d + (size_t)B * C;
    float* out_amax   = out_h + (size_t)B * C;

    cudaFuncSetAttribute(rec_kernel, cudaFuncAttributeMaxDynamicSharedMemorySize, RSMEM);
    cudaFuncSetAttribute(pre_gemm_bf16, cudaFuncAttributeMaxDynamicSharedMemorySize, GSMEM);
    cudaFuncSetAttribute(out_gemm_bf16, cudaFuncAttributeMaxDynamicSharedMemorySize, GSMEM);

    wprep_rec<<<NCG * 32 * C / 256, 256>>>(g_w, a_w);
    xprep<<<(B * T * F) / 256, 256>>>(x);
    pwprep<<<(3 * C * F) / 256, 256>>>(u_w, g_w, a_w);
    owprep<<<(KOUT * C) / 256, 256>>>(o_w);
    hinit<<<(BC + 255) / 256, 256>>>(h0, s, out_s);
    pre_gemm_bf16<<<dim3(512, 48), 256, GSMEM>>>(u_b, g_b);
    rec_kernel<<<RCTA, RTHR, RSMEM>>>(n0, d0, amax0,
                                      out_n, out_d, out_h, out_amax);
    out_gemm_bf16<<<dim3(512, 4), 256, GSMEM>>>(o_b, out_outs);
}

// round 16
// speedup vs baseline: 2.2119x; 1.0151x over previous
#include <cuda_runtime.h>
#include <cuda_bf16.h>
#include <cstdint>

#define B 64
#define T 512
#define F 256
#define C 1024
#define KOUT 256
#define BC (B * C)
#define WROW (F + C)          // 1280 floats per g_w/a_w row

// ---------------- recurrent kernel config --------------------------------
#define RCTA 128              // (cg 0..63) x (batch-half 0..1)
#define NCG  64               // cell groups
#define RTHR 544              // 16 compute warps + 1 sync-relay warp
#define NCW  512              // compute threads
#define CPC  16               // cells per CTA  (A tile M = 32 = 16 a + 16 g)
#define NB   32               // batches per CTA
#define APITCH 1032           // smem A pitch (bf16)
#define A_BYTES (64 * APITCH * 2)              // 132096
// warp-private B ring: 4 stages x 1280 B (2 halves x 8 rows x 80 B)
#define WB_STG 1280
#define WB_NSTG 4
#define WB_WARP (WB_NSTG * WB_STG)             // 5120
#define WB_OFF A_BYTES
#define RED_OFF (WB_OFF + 16 * WB_WARP)        // 214016
#define MBOX_OFF (RED_OFF + 16384)             // 230400
#define RSMEM (MBOX_OFF + 64)                  // 230464

// ---------------- bf16 GEMM (pre/out) config -----------------------------
#define GP 72                                   // smem pitch (bf16)
#define GSTG (128 * GP * 2)                     // 18432 B per operand stage
#define GSTAGE (2 * GSTG)                       // 36864
#define GSMEM (3 * GSTAGE)                      // 110592

// ---------------- device scratch -----------------------------------------
__device__ __align__(16) float g_U [(size_t)T * BC];
__device__ __align__(16) float g_GX[(size_t)T * BC];
__device__ __align__(16) float g_AX[(size_t)T * BC];
__device__ __align__(16) __nv_bfloat16 g_hshi[(size_t)(T + 1) * BC]; // h slots
__device__ __align__(16) __nv_bfloat16 g_hslo[(size_t)(T + 1) * BC];
__device__ __align__(16) __nv_bfloat16 g_Awhi[NCG * 32 * C];  // rec weights
__device__ __align__(16) __nv_bfloat16 g_Awlo[NCG * 32 * C];
__device__ __align__(16) __nv_bfloat16 g_xhi[(size_t)B * T * F];
__device__ __align__(16) __nv_bfloat16 g_xlo[(size_t)B * T * F];
__device__ __align__(16) __nv_bfloat16 g_pwhi[3 * C * F];     // u/gF/aF rows
__device__ __align__(16) __nv_bfloat16 g_pwlo[3 * C * F];
__device__ __align__(16) __nv_bfloat16 g_owhi[KOUT * C];
__device__ __align__(16) __nv_bfloat16 g_owlo[KOUT * C];
__device__ __align__(32) unsigned g_flag[2][8];

// ---------------- helpers -------------------------------------------------
__device__ __forceinline__ uint32_t smem_u32(const void* p) {
    uint32_t a;
    asm("{ .reg .u64 t; cvta.to.shared.u64 t, %1; cvt.u32.u64 %0, t; }"
        : "=r"(a) : "l"(p));
    return a;
}
__device__ __forceinline__ void cpa16(uint32_t dst, const void* src) {
    asm volatile("cp.async.cg.shared.global [%0], [%1], 16;"
                 :: "r"(dst), "l"(src) : "memory");
}
#define CPA_COMMIT() asm volatile("cp.async.commit_group;" ::: "memory")
#define CPA_WAIT(n)  asm volatile("cp.async.wait_group %0;" :: "n"(n) : "memory")

__device__ __forceinline__ void mma16816(float* d, const uint32_t* a,
                                         const uint32_t* b) {
    asm volatile(
        "mma.sync.aligned.m16n8k16.row.col.f32.bf16.bf16.f32 "
        "{%0,%1,%2,%3},{%4,%5,%6,%7},{%8,%9},{%0,%1,%2,%3};"
        : "+f"(d[0]), "+f"(d[1]), "+f"(d[2]), "+f"(d[3])
        : "r"(a[0]), "r"(a[1]), "r"(a[2]), "r"(a[3]), "r"(b[0]), "r"(b[1]));
}
__device__ __forceinline__ void ldm_x4(uint32_t* r, uint32_t a) {
    asm volatile("ldmatrix.sync.aligned.m8n8.x4.shared.b16 {%0,%1,%2,%3}, [%4];"
                 : "=r"(r[0]), "=r"(r[1]), "=r"(r[2]), "=r"(r[3]) : "r"(a));
}
__device__ __forceinline__ void ldm_x2(uint32_t* r, uint32_t a) {
    asm volatile("ldmatrix.sync.aligned.m8n8.x2.shared.b16 {%0,%1}, [%2];"
                 : "=r"(r[0]), "=r"(r[1]) : "r"(a));
}
__device__ __forceinline__ void split_bf16(float v, __nv_bfloat16& hi,
                                           __nv_bfloat16& lo) {
    hi = __float2bfloat16_rn(v);
    lo = __float2bfloat16_rn(v - __bfloat162float(hi));
}
__device__ __forceinline__ float tanh_fast(float x) {
    float y;
    asm("tanh.approx.f32 %0, %1;" : "=f"(y) : "f"(x));
    return y;
}

// ---------------- prep kernels -------------------------------------------
__global__ void wprep_rec(const float* __restrict__ g_w,
                          const float* __restrict__ a_w) {
    int idx = blockIdx.x * blockDim.x + threadIdx.x;   // NCG*32*C
    int cg = idx >> 15, r = (idx >> 10) & 31, k = idx & 1023;
    int cell = cg * CPC + (r & 15);
    const float* src = (r < 16) ? a_w : g_w;
    split_bf16(src[(size_t)cell * WROW + F + k], g_Awhi[idx], g_Awlo[idx]);
}
__global__ void xprep(const float* __restrict__ x) {
    size_t i = (size_t)blockIdx.x * blockDim.x + threadIdx.x;   // B*T*F
    split_bf16(x[i], g_xhi[i], g_xlo[i]);
}
__global__ void pwprep(const float* __restrict__ u_w,
                       const float* __restrict__ g_w,
                       const float* __restrict__ a_w) {
    int idx = blockIdx.x * blockDim.x + threadIdx.x;   // 3*C*F
    int row = idx >> 8, k = idx & 255;
    float v;
    if (row < C)           v = u_w[(size_t)row * F + k];
    else if (row < 2 * C)  v = g_w[(size_t)(row - C) * WROW + k];
    else                   v = a_w[(size_t)(row - 2 * C) * WROW + k];
    split_bf16(v, g_pwhi[idx], g_pwlo[idx]);
}
__global__ void owprep(const float* __restrict__ o_w) {
    int idx = blockIdx.x * blockDim.x + threadIdx.x;   // KOUT*C
    split_bf16(o_w[idx], g_owhi[idx], g_owlo[idx]);
}
__global__ void hinit(const float* __restrict__ h_in,
                      const float* __restrict__ s,
                      float* __restrict__ out_s) {
    int i = blockIdx.x * blockDim.x + threadIdx.x;
    if (i < BC) {
        int c = i & (C - 1);
        split_bf16(h_in[i] + tanhf(s[c]), g_hshi[i], g_hslo[i]);
    }
    if (i < C) out_s[i] = s[i];
    if (i < 16) ((unsigned*)g_flag)[i] = 0u;
}

// ---------------- generic bf16x3 GEMM bodies -----------------------------
struct GemmFrag {
    uint32_t aoff_h[2], aoff_l[2], boff_h[2], boff_l[2];
    int wm, wn, gid, tig, lane;
};
__device__ __forceinline__ GemmFrag gemm_frag(int tid) {
    GemmFrag f;
    int warp = tid >> 5;
    f.lane = tid & 31;
    f.gid = f.lane >> 2;
    f.tig = f.lane & 3;
    f.wm = warp & 1;
    f.wn = warp >> 1;
    int aRow = ((f.lane >> 3) & 1) * 8 + (f.lane & 7);
    int aCol = ((f.lane >> 4) & 1) * 8;
    int bRow = f.lane & 7;
    int bCol = ((f.lane >> 3) & 1) * 8;
#pragma unroll
    for (int mt = 0; mt < 2; ++mt) {
        f.aoff_h[mt] = (uint32_t)((f.wm * 32 + mt * 16 + aRow) * GP + aCol) * 2;
        f.aoff_l[mt] = (uint32_t)((64 + f.wm * 32 + mt * 16 + aRow) * GP + aCol) * 2;
    }
#pragma unroll
    for (int nt = 0; nt < 2; ++nt) {
        f.boff_h[nt] = (uint32_t)((f.wn * 16 + nt * 8 + bRow) * GP + bCol) * 2;
        f.boff_l[nt] = (uint32_t)((64 + f.wn * 16 + nt * 8 + bRow) * GP + bCol) * 2;
    }
    return f;
}
__device__ __forceinline__ void gemm_load_stage(
    uint32_t sb, int stg,
    const __nv_bfloat16* __restrict__ Ahi, const __nv_bfloat16* __restrict__ Alo,
    int lda,
    const __nv_bfloat16* __restrict__ Bhi, const __nv_bfloat16* __restrict__ Blo,
    int ldb, int k0, int tid) {
    uint32_t base = sb + stg * GSTAGE;
#pragma unroll
    for (int j = 0; j < 4; ++j) {
        int g = tid + j * 256;
        int row = g >> 3, q = g & 7;
        const __nv_bfloat16* src = (row < 64)
            ? Ahi + (size_t)row * lda + k0 + q * 8
            : Alo + (size_t)(row - 64) * lda + k0 + q * 8;
        cpa16(base + (uint32_t)(row * GP + q * 8) * 2, src);
    }
#pragma unroll
    for (int j = 0; j < 4; ++j) {
        int g = tid + j * 256;
        int row = g >> 3, q = g & 7;
        const __nv_bfloat16* src = (row < 64)
            ? Bhi + (size_t)row * ldb + k0 + q * 8
            : Blo + (size_t)(row - 64) * ldb + k0 + q * 8;
        cpa16(base + GSTG + (uint32_t)(row * GP + q * 8) * 2, src);
    }
    CPA_COMMIT();
}
__device__ __forceinline__ void gemm_mma_chunk(uint32_t sb, int stg,
                                               const GemmFrag& f,
                                               float acc[2][2][4]) {
    uint32_t stA = sb + stg * GSTAGE;
    uint32_t stB = stA + GSTG;
#pragma unroll
    for (int ks = 0; ks < 4; ++ks) {
        uint32_t kk = ks * 32;                 // bytes
        uint32_t ah[2][4], al[2][4], bh[2][2], bl[2][2];
#pragma unroll
        for (int mt = 0; mt < 2; ++mt) {
            ldm_x4(ah[mt], stA + f.aoff_h[mt] + kk);
            ldm_x4(al[mt], stA + f.aoff_l[mt] + kk);
        }
#pragma unroll
        for (int nt = 0; nt < 2; ++nt) {
            ldm_x2(bh[nt], stB + f.boff_h[nt] + kk);
            ldm_x2(bl[nt], stB + f.boff_l[nt] + kk);
        }
#pragma unroll
        for (int mt = 0; mt < 2; ++mt)
#pragma unroll
            for (int nt = 0; nt < 2; ++nt) {
                mma16816(acc[mt][nt], ah[mt], bh[nt]);
                mma16816(acc[mt][nt], ah[mt], bl[nt]);
                mma16816(acc[mt][nt], al[mt], bh[nt]);
            }
    }
}
__device__ __forceinline__ void gemm_transpose(char* smem, const GemmFrag& f,
                                               float acc[2][2][4]) {
    __syncthreads();
    float* tr = (float*)smem;                  // [n 64][m 64+4]
#pragma unroll
    for (int mt = 0; mt < 2; ++mt)
#pragma unroll
        for (int nt = 0; nt < 2; ++nt)
#pragma unroll
            for (int j = 0; j < 4; ++j) {
                int n = f.wn * 16 + nt * 8 + 2 * f.tig + (j & 1);
                int m = f.wm * 32 + mt * 16 + f.gid + (j >> 1) * 8;
                tr[n * 68 + m] = acc[mt][nt][j];
            }
    __syncthreads();
}

// ---------------- pre GEMM: [U|GX|AX] = x @ W^T + bias -------------------
__global__ void __launch_bounds__(256) pre_gemm_bf16(
    const float* __restrict__ u_b, const float* __restrict__ g_b) {
    extern __shared__ char smem[];
    const uint32_t sb = smem_u32(smem);
    const int tid = threadIdx.x;
    const int n0 = blockIdx.x * 64;            // x rows
    const int m0 = blockIdx.y * 64;            // weight rows (0..3071)
    const GemmFrag f = gemm_frag(tid);

    const __nv_bfloat16* Ahi = g_pwhi + (size_t)m0 * F;
    const __nv_bfloat16* Alo = g_pwlo + (size_t)m0 * F;
    const __nv_bfloat16* Bhi = g_xhi + (size_t)n0 * F;
    const __nv_bfloat16* Blo = g_xlo + (size_t)n0 * F;

    float acc[2][2][4] = {};
    const int NC = F / 64;                     // 4 chunks
    gemm_load_stage(sb, 0, Ahi, Alo, F, Bhi, Blo, F, 0, tid);
    gemm_load_stage(sb, 1, Ahi, Alo, F, Bhi, Blo, F, 64, tid);
    gemm_load_stage(sb, 2, Ahi, Alo, F, Bhi, Blo, F, 128, tid);
#pragma unroll 1
    for (int c = 0; c < NC; ++c) {
        int pend = NC - 1 - c;
        if (pend >= 2) CPA_WAIT(2); else if (pend == 1) CPA_WAIT(1); else CPA_WAIT(0);
        __syncthreads();
        gemm_mma_chunk(sb, c % 3, f, acc);
        if (c + 3 < NC) {
            __syncthreads();
            gemm_load_stage(sb, c % 3, Ahi, Alo, F, Bhi, Blo, F, (c + 3) * 64, tid);
        }
    }
    gemm_transpose(smem, f, acc);

    const int which = m0 >> 10;
    const int cbase = m0 & 1023;
    float* dst = (which == 0) ? g_U : (which == 1) ? g_GX : g_AX;
    const float* bias = (which == 0) ? u_b : (which == 1) ? g_b : nullptr;
    const float* tr = (const float*)smem;
    const int n = tid >> 2;
    const int n_g = n0 + n;
    const int b = n_g >> 9, t = n_g & 511;     // n_g = b*T + t
    float* drow = dst + (size_t)t * BC + (size_t)b * C + cbase;
#pragma unroll
    for (int q = 0; q < 4; ++q) {
        int m = ((tid & 3) * 4 + q) * 4;
        float4 v = *(const float4*)&tr[n * 68 + m];
        if (bias) {
            float4 bv = *(const float4*)&bias[cbase + m];
            v.x += bv.x; v.y += bv.y; v.z += bv.z; v.w += bv.w;
        }
        *(float4*)&drow[m] = v;
    }
}

// ---------------- out GEMM: outs[b][t][:] = h_t @ o_w^T + o_b ------------
__global__ void __launch_bounds__(256) out_gemm_bf16(
    const float* __restrict__ o_b, float* __restrict__ outp) {
    extern __shared__ char smem[];
    const uint32_t sb = smem_u32(smem);
    const int tid = threadIdx.x;
    const int tslot = blockIdx.x;              // t: h_t stored at slot t+1
    const int m0 = blockIdx.y * 64;            // out-class rows
    const GemmFrag f = gemm_frag(tid);

    const __nv_bfloat16* Ahi = g_owhi + (size_t)m0 * C;
    const __nv_bfloat16* Alo = g_owlo + (size_t)m0 * C;
    const __nv_bfloat16* Bhi = g_hshi + (size_t)(tslot + 1) * BC;
    const __nv_bfloat16* Blo = g_hslo + (size_t)(tslot + 1) * BC;

    float acc[2][2][4] = {};
    const int NC = C / 64;                     // 16 chunks
    gemm_load_stage(sb, 0, Ahi, Alo, C, Bhi, Blo, C, 0, tid);
    gemm_load_stage(sb, 1, Ahi, Alo, C, Bhi, Blo, C, 64, tid);
    gemm_load_stage(sb, 2, Ahi, Alo, C, Bhi, Blo, C, 128, tid);
#pragma unroll 1
    for (int c = 0; c < NC; ++c) {
        int pend = NC - 1 - c;
        if (pend >= 2) CPA_WAIT(2); else if (pend == 1) CPA_WAIT(1); else CPA_WAIT(0);
        __syncthreads();
        gemm_mma_chunk(sb, c % 3, f, acc);
        if (c + 3 < NC) {
            __syncthreads();
            gemm_load_stage(sb, c % 3, Ahi, Alo, C, Bhi, Blo, C, (c + 3) * 64, tid);
        }
    }
    gemm_transpose(smem, f, acc);

    const float* tr = (const float*)smem;
    const int b = tid >> 2;                    // n index = batch
    float* drow = outp + (size_t)b * T * KOUT + (size_t)tslot * KOUT + m0;
#pragma unroll
    for (int q = 0; q < 4; ++q) {
        int m = ((tid & 3) * 4 + q) * 4;
        float4 v = *(const float4*)&tr[b * 68 + m];
        float4 bv = *(const float4*)&o_b[m0 + m];
        v.x += bv.x; v.y += bv.y; v.z += bv.z; v.w += bv.w;
        *(float4*)&drow[m] = v;
    }
}

// ---------------- warp-private B slice loader ----------------------------
__device__ __forceinline__ void rec_load_my(
    int p, int s, uint32_t wb, const __nv_bfloat16* __restrict__ hhi,
    const __nv_bfloat16* __restrict__ hlo, int bbase, int wn, int kq,
    int lane) {
#pragma unroll
    for (int j = 0; j < 2; ++j) {
        int i = lane * 2 + j;                  // 0..63
        int half = i >> 5, r = (i >> 2) & 7, q = i & 3;
        uint32_t d = wb + s * WB_STG + half * 640 + r * 80 + q * 16;
        const __nv_bfloat16* src = (half ? hlo : hhi)
            + (size_t)(bbase + wn * 8 + r) * C + p * 128 + kq * 32 + q * 8;
        cpa16(d, src);
    }
    CPA_COMMIT();
}
// compute-warp spin on smem mailbox (no L2 traffic)
__device__ __forceinline__ void mbox_wait(volatile unsigned* m, unsigned tgt) {
    while (*m < tgt) {}
}

// ---------------- persistent recurrent kernel ----------------------------
// 16 compute warps + 1 sync-relay warp; per-chunk smem-mailbox gating;
// own chunk consumed LAST to hide own release->relay latency.
__global__ void __launch_bounds__(RTHR, 1) rec_kernel(
    const float* __restrict__ n_in, const float* __restrict__ d_in,
    const float* __restrict__ amax_in,
    float* __restrict__ out_n, float* __restrict__ out_d,
    float* __restrict__ out_h, float* __restrict__ out_amax) {
    extern __shared__ char smem[];
    const uint32_t sb = smem_u32(smem);
    float* red = (float*)(smem + RED_OFF);     // [4 kq][8 q][128]
    volatile unsigned* mbox = (volatile unsigned*)(smem + MBOX_OFF);

    const int tid   = threadIdx.x;
    const int warp  = tid >> 5;
    const int lane  = tid & 31;
    const bool comp = (warp < 16);
    const int wn    = warp & 3;
    const int kq    = warp >> 2;               // valid for comp warps
    const int cg    = blockIdx.x >> 1;
    const int bh    = blockIdx.x & 1;
    const int bbase = bh * NB;
    const int rot   = cg >> 3;                 // own chunk group
    const int start = (rot + 1) & 7;           // consume own chunk LAST
    const uint32_t wb = sb + WB_OFF + warp * WB_WARP;

    // ---- prologue: resident weights into smem (all warps help) ----
    for (int i = tid; i < 64 * 128; i += RTHR) {
        int row = i >> 7, q = i & 127;
        const __nv_bfloat16* src = (row < 32)
            ? g_Awhi + ((size_t)cg * 32 + row) * C + q * 8
            : g_Awlo + ((size_t)cg * 32 + row - 32) * C + q * 8;
        cpa16(sb + (uint32_t)(row * APITCH + q * 8) * 2, src);
    }
    CPA_COMMIT();
    if (tid < 8) mbox[tid] = 0u;
    CPA_WAIT(0);
    __syncthreads();                           // A tile + mailbox visible

    const int aRow = ((lane >> 3) & 1) * 8 + (lane & 7);
    const int aCol = ((lane >> 4) & 1) * 8;
    const uint32_t aHi0 = sb + (uint32_t)((aRow)      * APITCH + aCol) * 2;
    const uint32_t aHi1 = sb + (uint32_t)((16 + aRow) * APITCH + aCol) * 2;
    const uint32_t aLo0 = sb + (uint32_t)((32 + aRow) * APITCH + aCol) * 2;
    const uint32_t aLo1 = sb + (uint32_t)((48 + aRow) * APITCH + aCol) * 2;
    const uint32_t bBase = wb + (uint32_t)(lane >> 4) * 640
                         + (uint32_t)(lane & 7) * 80
                         + (uint32_t)((lane >> 3) & 1) * 16;

    // ---- per-thread state (compute threads only) ----
    const int cc = tid & 15;
    const int nb = (tid >> 4) & 31;
    const int bglob = bbase + nb;
    const int cglob = cg * CPC + cc;
    const int p2 = ((cc >> 3) << 1) | (nb & 1);
    const int lane_src = ((cc & 7) << 2) | ((nb & 7) >> 1);
    const int wn_src = nb >> 3;
    const int aidx_base = wn_src * 32 + lane_src;

    float sn = 0.f, sd = 0.f, sa = 0.f;
    if (comp) {
        sn = n_in[bglob * C + cglob];
        sd = d_in[bglob * C + cglob];
        sa = amax_in[bglob * C + cglob];
    }

    for (int t = 0; t < T; ++t) {
        const __nv_bfloat16* hhi = g_hshi + (size_t)t * BC;
        const __nv_bfloat16* hlo = g_hslo + (size_t)t * BC;
        const unsigned tgt = 8u * (unsigned)t;

        if (!comp) {
            // ---- sync-relay warp: poll L2 flags, publish to smem mailbox ----
            unsigned done = (lane < 8) ? 0u : 1u;
            const unsigned* fp = &g_flag[bh][lane & 7];
            while (__ballot_sync(0xFFFFFFFFu, done) != 0xFFFFFFFFu) {
                if (!done) {
                    unsigned v;
                    asm volatile("ld.volatile.global.u32 %0, [%1];"
                                 : "=r"(v) : "l"(fp));
                    if (v >= tgt) { mbox[lane] = v; done = 1u; }
                }
            }
        } else {
            // ---- compute warps: per-chunk gated, barrier-free k-loop ----
            const size_t tb = (size_t)t * BC;
            const size_t eidx = tb + (size_t)bglob * C + cglob;
            float ax = __ldg(&g_AX[eidx]);
            float gx = __ldg(&g_GX[eidx]);
            float ux = __ldg(&g_U[eidx]);

            mbox_wait(mbox + start, tgt);
            rec_load_my(start, 0, wb, hhi, hlo, bbase, wn, kq, lane);
            {
                const int c1 = (start + 1) & 7;
                mbox_wait(mbox + c1, tgt);
                rec_load_my(c1, 1, wb, hhi, hlo, bbase, wn, kq, lane);
            }
            {
                const int c2 = (start + 2) & 7;
                mbox_wait(mbox + c2, tgt);
                rec_load_my(c2, 2, wb, hhi, hlo, bbase, wn, kq, lane);
            }

            float acc[8];
#pragma unroll
            for (int q = 0; q < 8; ++q) acc[q] = 0.f;

#pragma unroll 1
            for (int i = 0; i < 8; ++i) {
                const int p = (start + i) & 7;
                if (i <= 5) CPA_WAIT(2);
                else if (i == 6) CPA_WAIT(1);
                else CPA_WAIT(0);
                if (i < 5) {
                    const int pn = (start + i + 3) & 7;
                    mbox_wait(mbox + pn, tgt);
                    rec_load_my(pn, (i + 3) & 3, wb, hhi, hlo, bbase, wn, kq,
                                lane);
                }
                const uint32_t bs = bBase + (uint32_t)((i & 3) * WB_STG);
#pragma unroll
                for (int ks = 0; ks < 2; ++ks) {
                    const int ka = p * 128 + kq * 32 + ks * 16;
                    uint32_t ah0[4], ah1[4], al0[4], al1[4], bf[4];
                    ldm_x4(ah0, aHi0 + ka * 2);
                    ldm_x4(ah1, aHi1 + ka * 2);
                    ldm_x4(bf,  bs + ks * 32);
                    ldm_x4(al0, aLo0 + ka * 2);
                    ldm_x4(al1, aLo1 + ka * 2);
                    mma16816(acc + 0, ah0, bf);
                    mma16816(acc + 4, ah1, bf);
                    mma16816(acc + 0, ah0, bf + 2);
                    mma16816(acc + 4, ah1, bf + 2);
                    mma16816(acc + 0, al0, bf);
                    mma16816(acc + 4, al1, bf);
                }
            }

            float* dst = red + (kq * 8) * 128 + wn * 32 + lane;
#pragma unroll
            for (int q = 0; q < 8; ++q) dst[q * 128] = acc[q];

            __syncthreads();                   // barrier 1 (partials ready)
            {
                float at = ax, gt = gx;
#pragma unroll
                for (int k2 = 0; k2 < 4; ++k2) {
                    at += red[(k2 * 8 + p2) * 128 + aidx_base];
                    gt += red[(k2 * 8 + 4 + p2) * 128 + aidx_base];
                }
                float z  = ux * tanh_fast(gt);
                float an = fmaxf(sa, at);
                float ed = __expf(sa - an);
                float es = __expf(at - an);
                sn = sn * ed + z * es;
                sd = sd * ed + es;
                float h = tanh_fast(sn / sd);
                sa = an;
                __nv_bfloat16 hi, lo;
                split_bf16(h, hi, lo);
                g_hshi[(size_t)(t + 1) * BC + bglob * C + cglob] = hi;
                g_hslo[(size_t)(t + 1) * BC + bglob * C + cglob] = lo;
            }
            __syncthreads();                   // barrier 2 (h stores done)
            if (tid == 0) {
                __threadfence();
                atomicAdd(&g_flag[bh][rot], 1u);
            }
            continue;
        }
        // sync warp joins the two per-step barriers
        __syncthreads();                       // barrier 1
        __syncthreads();                       // barrier 2
    }

    if (comp) {
        out_n[bglob * C + cglob]    = sn;
        out_d[bglob * C + cglob]    = sd;
        out_h[bglob * C + cglob]    = tanh_fast(sn / sd);
        out_amax[bglob * C + cglob] = sa;
    }
}

// ---------------- launch ---------------------------------------------------
extern "C" void kernel_launch(void* const* d_in, const int* in_sizes, int n_in,
                              void* d_out, int out_size) {
    (void)in_sizes; (void)n_in; (void)out_size;
    const float* x      = (const float*)d_in[0];
    const float* s      = (const float*)d_in[1];
    const float* n0     = (const float*)d_in[2];
    const float* d0     = (const float*)d_in[3];
    const float* h0     = (const float*)d_in[4];
    const float* amax0  = (const float*)d_in[5];
    const float* u_w    = (const float*)d_in[6];
    const float* u_b    = (const float*)d_in[7];
    const float* g_w    = (const float*)d_in[8];
    const float* g_b    = (const float*)d_in[9];
    const float* a_w    = (const float*)d_in[10];
    const float* o_w    = (const float*)d_in[11];
    const float* o_b    = (const float*)d_in[12];

    float* out        = (float*)d_out;
    float* out_outs   = out;
    float* out_s      = out + (size_t)B * T * KOUT;
    float* out_n      = out_s + C;
    float* out_d      = out_n + (size_t)B * C;
    float* out_h      = out_d + (size_t)B * C;
    float* out_amax   = out_h + (size_t)B * C;

    cudaFuncSetAttribute(rec_kernel, cudaFuncAttributeMaxDynamicSharedMemorySize, RSMEM);
    cudaFuncSetAttribute(pre_gemm_bf16, cudaFuncAttributeMaxDynamicSharedMemorySize, GSMEM);
    cudaFuncSetAttribute(out_gemm_bf16, cudaFuncAttributeMaxDynamicSharedMemorySize, GSMEM);

    wprep_rec<<<NCG * 32 * C / 256, 256>>>(g_w, a_w);
    xprep<<<(B * T * F) / 256, 256>>>(x);
    pwprep<<<(3 * C * F) / 256, 256>>>(u_w, g_w, a_w);
    owprep<<<(KOUT * C) / 256, 256>>>(o_w);
    hinit<<<(BC + 255) / 256, 256>>>(h0, s, out_s);
    pre_gemm_bf16<<<dim3(512, 48), 256, GSMEM>>>(u_b, g_b);
    rec_kernel<<<RCTA, RTHR, RSMEM>>>(n0, d0, amax0,
                                      out_n, out_d, out_h, out_amax);
    out_gemm_bf16<<<dim3(512, 4), 256, GSMEM>>>(o_b, out_outs);
}